// round 1
// baseline (speedup 1.0000x reference)
#include <cuda_runtime.h>
#include <math.h>

#define Bb      64
#define T       512
#define D       2048
#define NBUF    16384
#define ROUNDS  10

// ---------------- scratch (static device globals; no allocation) -------------
__device__ float d_pooled[Bb * D];
__device__ float d_query[Bb * D];
__device__ float d_base[Bb * NBUF];
__device__ float d_E[Bb * NBUF];
__device__ float d_AW[Bb * NBUF];
__device__ float d_g[NBUF];
__device__ float d_validf[NBUF];
__device__ float d_wages[NBUF];
__device__ float d_rowsum[Bb];
__device__ float d_C1[Bb * D];
__device__ float d_part[8 * Bb * D];
__device__ float d_activeSum;
__device__ float d_wsum;
__device__ float d_incw;
__device__ float d_incflag;
__device__ int   d_stopped;

// ---------------- valid_mask dtype detection + conversion --------------------
// bool may arrive as u8 / int32 / float32. Detect via value patterns:
//   f32 ones -> floats exactly 0.0/1.0 ; i32 ones -> ints in {0,1} ;
//   u8  ones -> neither pattern holds.
__global__ void k_detect(const void* vm) {
    __shared__ int mode;
    if (threadIdx.x == 0) {
        const float* fp = (const float*)vm;
        const int*   ip = (const int*)vm;
        bool isF = true, isI = true;
        for (int k = 0; k < 64; k++) {
            float f = fp[k];
            if (!(f == 0.0f || f == 1.0f)) isF = false;
            int v = ip[k];
            if (!(v == 0 || v == 1)) isI = false;
        }
        mode = isF ? 2 : (isI ? 1 : 0);
    }
    __syncthreads();
    int m = mode;
    const unsigned char* cp = (const unsigned char*)vm;
    const int*   ip = (const int*)vm;
    const float* fp = (const float*)vm;
    for (int n = threadIdx.x; n < NBUF; n += blockDim.x) {
        float v;
        if (m == 2)      v = (fp[n] != 0.0f) ? 1.f : 0.f;
        else if (m == 1) v = (ip[n] != 0)    ? 1.f : 0.f;
        else             v = (cp[n] != 0)    ? 1.f : 0.f;
        d_validf[n] = v;
    }
}

// ---------------- init: zero AW, copy ages, zero scalars ----------------------
__global__ void k_init(const float* __restrict__ ages) {
    int i = blockIdx.x * 256 + threadIdx.x;
    if (i < Bb * NBUF) d_AW[i] = 0.f;
    if (i < NBUF)      d_wages[i] = ages[i];
    if (i == 0) { d_activeSum = 0.f; d_wsum = 0.f; d_stopped = 0; }
}

// ---------------- masked mean pool -------------------------------------------
__global__ void __launch_bounds__(256) k_pool(const float* __restrict__ qs,
                                              const float* __restrict__ mask) {
    int b = blockIdx.y;
    int d = blockIdx.x * 256 + threadIdx.x;
    __shared__ float sm[T];
    __shared__ float red[256];
    for (int t = threadIdx.x; t < T; t += 256) sm[t] = mask[b * T + t];
    __syncthreads();
    red[threadIdx.x] = sm[threadIdx.x] + sm[threadIdx.x + 256];
    __syncthreads();
    for (int off = 128; off > 0; off >>= 1) {
        if (threadIdx.x < off) red[threadIdx.x] += red[threadIdx.x + off];
        __syncthreads();
    }
    float msum = red[0];
    const float* base = qs + ((size_t)b * T) * D + d;
    float a0 = 0, a1 = 0, a2 = 0, a3 = 0;
    for (int t = 0; t < T; t += 4) {
        a0 += base[(size_t)(t + 0) * D] * sm[t + 0];
        a1 += base[(size_t)(t + 1) * D] * sm[t + 1];
        a2 += base[(size_t)(t + 2) * D] * sm[t + 2];
        a3 += base[(size_t)(t + 3) * D] * sm[t + 3];
    }
    d_pooled[b * D + d] = (a0 + a1 + a2 + a3) / (msum + 1e-8f);
}

// ---------------- proj GEMM (A[64xD] @ W^T[DxD]), split-K=8 -------------------
// grid (16 n-tiles, 8 k-slices), block 256, tile 64x128, micro 4x8
__global__ void __launch_bounds__(256) k_proj(const float* __restrict__ W, int useC1) {
    const float* A = useC1 ? d_C1 : d_pooled;
    const int n0 = blockIdx.x * 128;
    const int kbase = blockIdx.y * 256;
    __shared__ float As[32][64];
    __shared__ float Bs[32][128];
    const int tid = threadIdx.x;
    const int tx = tid & 15, ty = tid >> 4;
    float acc[4][8];
#pragma unroll
    for (int i = 0; i < 4; i++)
#pragma unroll
        for (int j = 0; j < 8; j++) acc[i][j] = 0.f;

    for (int kc = 0; kc < 256; kc += 32) {
        int k0 = kbase + kc;
#pragma unroll
        for (int j = 0; j < 2; j++) {
            int idx = tid * 2 + j;
            int m = idx >> 3, c4 = idx & 7;
            float4 v = *(const float4*)&A[m * D + k0 + c4 * 4];
            As[c4 * 4 + 0][m] = v.x; As[c4 * 4 + 1][m] = v.y;
            As[c4 * 4 + 2][m] = v.z; As[c4 * 4 + 3][m] = v.w;
        }
#pragma unroll
        for (int j = 0; j < 4; j++) {
            int idx = tid * 4 + j;
            int n = idx >> 3, c4 = idx & 7;
            float4 v = *(const float4*)&W[(size_t)(n0 + n) * D + k0 + c4 * 4];
            Bs[c4 * 4 + 0][n] = v.x; Bs[c4 * 4 + 1][n] = v.y;
            Bs[c4 * 4 + 2][n] = v.z; Bs[c4 * 4 + 3][n] = v.w;
        }
        __syncthreads();
#pragma unroll
        for (int kk = 0; kk < 32; kk++) {
            float a[4], bb[8];
            *(float4*)a        = *(float4*)&As[kk][ty * 4];
            *(float4*)bb       = *(float4*)&Bs[kk][tx * 8];
            *(float4*)(bb + 4) = *(float4*)&Bs[kk][tx * 8 + 4];
#pragma unroll
            for (int i = 0; i < 4; i++)
#pragma unroll
                for (int j = 0; j < 8; j++) acc[i][j] = fmaf(a[i], bb[j], acc[i][j]);
        }
        __syncthreads();
    }
    float* o = d_part + ((size_t)blockIdx.y * Bb) * D;
#pragma unroll
    for (int i = 0; i < 4; i++)
#pragma unroll
        for (int j = 0; j < 8; j++)
            o[(ty * 4 + i) * D + n0 + tx * 8 + j] = acc[i][j];
}

__global__ void k_reduce_q(const float* __restrict__ bq) {
    int idx = blockIdx.x * 256 + threadIdx.x;
    if (idx >= Bb * D) return;
    float s = 0.f;
#pragma unroll
    for (int kz = 0; kz < 8; kz++) s += d_part[kz * Bb * D + idx];
    d_query[idx] = s + bq[idx & (D - 1)];
}

// ---------------- base_scores = query @ keys^T * inv_sqrt_d -------------------
// grid 128 (n-tiles of 128), block 256
__global__ void __launch_bounds__(256) k_base(const float* __restrict__ keys) {
    const int n0 = blockIdx.x * 128;
    __shared__ float As[32][64];
    __shared__ float Bs[32][128];
    const int tid = threadIdx.x;
    const int tx = tid & 15, ty = tid >> 4;
    float acc[4][8];
#pragma unroll
    for (int i = 0; i < 4; i++)
#pragma unroll
        for (int j = 0; j < 8; j++) acc[i][j] = 0.f;

    for (int k0 = 0; k0 < D; k0 += 32) {
#pragma unroll
        for (int j = 0; j < 2; j++) {
            int idx = tid * 2 + j;
            int m = idx >> 3, c4 = idx & 7;
            float4 v = *(const float4*)&d_query[m * D + k0 + c4 * 4];
            As[c4 * 4 + 0][m] = v.x; As[c4 * 4 + 1][m] = v.y;
            As[c4 * 4 + 2][m] = v.z; As[c4 * 4 + 3][m] = v.w;
        }
#pragma unroll
        for (int j = 0; j < 4; j++) {
            int idx = tid * 4 + j;
            int n = idx >> 3, c4 = idx & 7;
            float4 v = *(const float4*)&keys[(size_t)(n0 + n) * D + k0 + c4 * 4];
            Bs[c4 * 4 + 0][n] = v.x; Bs[c4 * 4 + 1][n] = v.y;
            Bs[c4 * 4 + 2][n] = v.z; Bs[c4 * 4 + 3][n] = v.w;
        }
        __syncthreads();
#pragma unroll
        for (int kk = 0; kk < 32; kk++) {
            float a[4], bb[8];
            *(float4*)a        = *(float4*)&As[kk][ty * 4];
            *(float4*)bb       = *(float4*)&Bs[kk][tx * 8];
            *(float4*)(bb + 4) = *(float4*)&Bs[kk][tx * 8 + 4];
#pragma unroll
            for (int i = 0; i < 4; i++)
#pragma unroll
                for (int j = 0; j < 8; j++) acc[i][j] = fmaf(a[i], bb[j], acc[i][j]);
        }
        __syncthreads();
    }
    const float scale = 0.022097086912079608f;  // 1/sqrt(2048)
#pragma unroll
    for (int i = 0; i < 4; i++)
#pragma unroll
        for (int j = 0; j < 8; j++)
            d_base[(size_t)(ty * 4 + i) * NBUF + n0 + tx * 8 + j] = acc[i][j] * scale;
}

// ---------------- round loop kernels ------------------------------------------
__global__ void __launch_bounds__(256) k_g(const float* __restrict__ prio) {
    int n = blockIdx.x * 256 + threadIdx.x;
    float w   = d_wages[n];
    float eff = prio[n] * __expf(w * (-0.105360515657826301f));  // 0.9^w
    float act = d_validf[n] / (1.f + __expf((0.5f - eff) * 10.f));
    d_g[n] = act * eff;
    __shared__ float red[256];
    red[threadIdx.x] = act;
    __syncthreads();
    for (int off = 128; off > 0; off >>= 1) {
        if (threadIdx.x < off) red[threadIdx.x] += red[threadIdx.x + off];
        __syncthreads();
    }
    if (threadIdx.x == 0) atomicAdd(&d_activeSum, red[0]);
}

__global__ void k_inc(float rw) {
    float s = d_activeSum;
    int st = d_stopped | ((s < 0.5f) ? 1 : 0);
    d_stopped = st;
    float inc = st ? 0.f : 1.f;
    d_incflag = inc;
    d_incw = inc * rw;
    d_wsum += inc * rw;
    d_activeSum = 0.f;
}

__global__ void __launch_bounds__(256) k_row() {
    int b = blockIdx.x;
    const float* br = d_base + (size_t)b * NBUF;
    float* er = d_E + (size_t)b * NBUF;
    float s = 0.f;
    for (int n = threadIdx.x; n < NBUF; n += 256) {
        float e = (d_validf[n] != 0.f) ? __expf(br[n] * d_g[n]) : 0.f;
        er[n] = e;
        s += e;
    }
    __shared__ float red[256];
    red[threadIdx.x] = s;
    __syncthreads();
    for (int off = 128; off > 0; off >>= 1) {
        if (threadIdx.x < off) red[threadIdx.x] += red[threadIdx.x + off];
        __syncthreads();
    }
    if (threadIdx.x == 0) d_rowsum[b] = red[0];
}

__global__ void __launch_bounds__(128) k_upd() {
    int n = blockIdx.x * 128 + threadIdx.x;
    __shared__ float inv[64];
    if (threadIdx.x < 64) inv[threadIdx.x] = 1.f / d_rowsum[threadIdx.x];
    __syncthreads();
    float incw = d_incw, incf = d_incflag;
    float cs = 0.f;
#pragma unroll 8
    for (int b = 0; b < 64; b++) {
        size_t idx = (size_t)b * NBUF + n;
        float a = d_E[idx] * inv[b];
        d_AW[idx] += incw * a;
        cs += a;
    }
    d_wages[n] += incf * cs * (1.f / 64.f);
}

// ---------------- C1 = AW @ values (split-K=8) --------------------------------
// grid (16 d-tiles, 8 k-slices of 2048), block 256, tile 64x128
__global__ void __launch_bounds__(256) k_av(const float* __restrict__ V) {
    const int d0 = blockIdx.x * 128;
    const int nbase = blockIdx.y * 2048;
    __shared__ float As[32][64];
    __shared__ float Bs[32][128];
    const int tid = threadIdx.x;
    const int tx = tid & 15, ty = tid >> 4;
    float acc[4][8];
#pragma unroll
    for (int i = 0; i < 4; i++)
#pragma unroll
        for (int j = 0; j < 8; j++) acc[i][j] = 0.f;

    for (int nc = 0; nc < 2048; nc += 32) {
        int n0 = nbase + nc;
#pragma unroll
        for (int j = 0; j < 2; j++) {
            int idx = tid * 2 + j;
            int m = idx >> 3, c4 = idx & 7;
            float4 v = *(const float4*)&d_AW[(size_t)m * NBUF + n0 + c4 * 4];
            As[c4 * 4 + 0][m] = v.x; As[c4 * 4 + 1][m] = v.y;
            As[c4 * 4 + 2][m] = v.z; As[c4 * 4 + 3][m] = v.w;
        }
#pragma unroll
        for (int j = 0; j < 4; j++) {
            int idx = tid * 4 + j;
            int nl = idx >> 5, d4 = idx & 31;
            *(float4*)&Bs[nl][d4 * 4] =
                *(const float4*)&V[(size_t)(n0 + nl) * D + d0 + d4 * 4];
        }
        __syncthreads();
#pragma unroll
        for (int kk = 0; kk < 32; kk++) {
            float a[4], bb[8];
            *(float4*)a        = *(float4*)&As[kk][ty * 4];
            *(float4*)bb       = *(float4*)&Bs[kk][tx * 8];
            *(float4*)(bb + 4) = *(float4*)&Bs[kk][tx * 8 + 4];
#pragma unroll
            for (int i = 0; i < 4; i++)
#pragma unroll
                for (int j = 0; j < 8; j++) acc[i][j] = fmaf(a[i], bb[j], acc[i][j]);
        }
        __syncthreads();
    }
    float* o = d_part + ((size_t)blockIdx.y * Bb) * D;
#pragma unroll
    for (int i = 0; i < 4; i++)
#pragma unroll
        for (int j = 0; j < 8; j++)
            o[(ty * 4 + i) * D + d0 + tx * 8 + j] = acc[i][j];
}

__global__ void k_reduce_c1() {
    int idx = blockIdx.x * 256 + threadIdx.x;
    if (idx >= Bb * D) return;
    float s = 0.f;
#pragma unroll
    for (int kz = 0; kz < 8; kz++) s += d_part[kz * Bb * D + idx];
    d_C1[idx] = s;
}

__global__ void k_reduce_out(const float* __restrict__ bc, float* __restrict__ out) {
    int idx = blockIdx.x * 256 + threadIdx.x;
    if (idx >= Bb * D) return;
    float ws = d_wsum;
    if (ws > 0.f) {
        float s = 0.f;
#pragma unroll
        for (int kz = 0; kz < 8; kz++) s += d_part[kz * Bb * D + idx];
        out[idx] = s / fmaxf(ws, 1e-8f) + bc[idx & (D - 1)];
    } else {
        out[idx] = 0.f;
    }
}

// ---------------- launch ------------------------------------------------------
extern "C" void kernel_launch(void* const* d_in, const int* in_sizes, int n_in,
                              void* d_out, int out_size) {
    const float* qs     = (const float*)d_in[0];
    const float* amask  = (const float*)d_in[1];
    const float* keys   = (const float*)d_in[2];
    const float* values = (const float*)d_in[3];
    const float* prio   = (const float*)d_in[4];
    const float* ages   = (const float*)d_in[5];
    const void*  vmask  = d_in[6];
    const float* Wq     = (const float*)d_in[7];
    const float* bq     = (const float*)d_in[8];
    const float* Wc     = (const float*)d_in[9];
    const float* bc     = (const float*)d_in[10];
    float* out = (float*)d_out;

    k_detect<<<1, 256>>>(vmask);
    k_init<<<(Bb * NBUF + 255) / 256, 256>>>(ages);
    k_pool<<<dim3(8, 64), 256>>>(qs, amask);
    k_proj<<<dim3(16, 8), 256>>>(Wq, 0);
    k_reduce_q<<<(Bb * D + 255) / 256, 256>>>(bq);
    k_base<<<128, 256>>>(keys);

    for (int r = 0; r < ROUNDS; r++) {
        float rw = (float)pow(0.9, (double)r);
        k_g<<<64, 256>>>(prio);
        k_inc<<<1, 1>>>(rw);
        k_row<<<64, 256>>>();
        k_upd<<<128, 128>>>();
    }

    k_av<<<dim3(16, 8), 256>>>(values);
    k_reduce_c1<<<(Bb * D + 255) / 256, 256>>>();
    k_proj<<<dim3(16, 8), 256>>>(Wc, 1);
    k_reduce_out<<<(Bb * D + 255) / 256, 256>>>(bc, out);
}

// round 2
// speedup vs baseline: 1.0410x; 1.0410x over previous
#include <cuda_runtime.h>
#include <math.h>

#define Bb      64
#define T       512
#define D       2048
#define NBUF    16384
#define ROUNDS  10
#define GRIDB   128

// ---------------- scratch (static device globals; no allocation) -------------
__device__ float d_pooled[Bb * D];
__device__ float d_query[Bb * D];
__device__ float d_base[Bb * NBUF];
__device__ float d_AW[Bb * NBUF];
__device__ float d_validf[NBUF];
__device__ float d_wages[NBUF];
__device__ float d_rs_part[2 * Bb];
__device__ float d_C1[Bb * D];
__device__ float d_part[4 * Bb * NBUF];   // 16 MB scratch, reused by all GEMMs
__device__ float d_wsum;
__device__ unsigned d_bar_cnt;
__device__ unsigned d_bar_gen;

// ---------------- valid_mask dtype detection + conversion --------------------
__global__ void k_detect(const void* vm) {
    __shared__ int mode;
    if (threadIdx.x == 0) {
        const float* fp = (const float*)vm;
        const int*   ip = (const int*)vm;
        bool isF = true, isI = true;
        for (int k = 0; k < 64; k++) {
            float f = fp[k];
            if (!(f == 0.0f || f == 1.0f)) isF = false;
            int v = ip[k];
            if (!(v == 0 || v == 1)) isI = false;
        }
        mode = isF ? 2 : (isI ? 1 : 0);
    }
    __syncthreads();
    int m = mode;
    const unsigned char* cp = (const unsigned char*)vm;
    const int*   ip = (const int*)vm;
    const float* fp = (const float*)vm;
    for (int n = threadIdx.x; n < NBUF; n += blockDim.x) {
        float v;
        if (m == 2)      v = (fp[n] != 0.0f) ? 1.f : 0.f;
        else if (m == 1) v = (ip[n] != 0)    ? 1.f : 0.f;
        else             v = (cp[n] != 0)    ? 1.f : 0.f;
        d_validf[n] = v;
    }
}

__global__ void k_init(const float* __restrict__ ages) {
    int i = blockIdx.x * 256 + threadIdx.x;
    if (i < Bb * NBUF) d_AW[i] = 0.f;
    if (i < NBUF)      d_wages[i] = ages[i];
    if (i == 0) { d_wsum = 0.f; }
}

// ---------------- masked mean pool -------------------------------------------
__global__ void __launch_bounds__(256) k_pool(const float* __restrict__ qs,
                                              const float* __restrict__ mask) {
    int b = blockIdx.y;
    int d = blockIdx.x * 256 + threadIdx.x;
    __shared__ float sm[T];
    __shared__ float red[256];
    for (int t = threadIdx.x; t < T; t += 256) sm[t] = mask[b * T + t];
    __syncthreads();
    red[threadIdx.x] = sm[threadIdx.x] + sm[threadIdx.x + 256];
    __syncthreads();
    for (int off = 128; off > 0; off >>= 1) {
        if (threadIdx.x < off) red[threadIdx.x] += red[threadIdx.x + off];
        __syncthreads();
    }
    float msum = red[0];
    const float* base = qs + ((size_t)b * T) * D + d;
    float a0 = 0, a1 = 0, a2 = 0, a3 = 0;
    for (int t = 0; t < T; t += 4) {
        a0 += base[(size_t)(t + 0) * D] * sm[t + 0];
        a1 += base[(size_t)(t + 1) * D] * sm[t + 1];
        a2 += base[(size_t)(t + 2) * D] * sm[t + 2];
        a3 += base[(size_t)(t + 3) * D] * sm[t + 3];
    }
    d_pooled[b * D + d] = (a0 + a1 + a2 + a3) / (msum + 1e-8f);
}

// ---------------- proj GEMM (A[64xD] @ W^T[DxD]), split-K=32 ------------------
// grid (16 n-tiles, 32 k-slices of 64), block 256, tile 64x128, micro 4x8
__global__ void __launch_bounds__(256) k_proj(const float* __restrict__ W, int useC1) {
    const float* A = useC1 ? d_C1 : d_pooled;
    const int n0 = blockIdx.x * 128;
    const int kbase = blockIdx.y * 64;
    __shared__ float As[32][64];
    __shared__ float Bs[32][128];
    const int tid = threadIdx.x;
    const int tx = tid & 15, ty = tid >> 4;
    float acc[4][8];
#pragma unroll
    for (int i = 0; i < 4; i++)
#pragma unroll
        for (int j = 0; j < 8; j++) acc[i][j] = 0.f;

    for (int kc = 0; kc < 64; kc += 32) {
        int k0 = kbase + kc;
#pragma unroll
        for (int j = 0; j < 2; j++) {
            int idx = tid * 2 + j;
            int m = idx >> 3, c4 = idx & 7;
            float4 v = *(const float4*)&A[m * D + k0 + c4 * 4];
            As[c4 * 4 + 0][m] = v.x; As[c4 * 4 + 1][m] = v.y;
            As[c4 * 4 + 2][m] = v.z; As[c4 * 4 + 3][m] = v.w;
        }
#pragma unroll
        for (int j = 0; j < 4; j++) {
            int idx = tid * 4 + j;
            int n = idx >> 3, c4 = idx & 7;
            float4 v = *(const float4*)&W[(size_t)(n0 + n) * D + k0 + c4 * 4];
            Bs[c4 * 4 + 0][n] = v.x; Bs[c4 * 4 + 1][n] = v.y;
            Bs[c4 * 4 + 2][n] = v.z; Bs[c4 * 4 + 3][n] = v.w;
        }
        __syncthreads();
#pragma unroll
        for (int kk = 0; kk < 32; kk++) {
            float a[4], bb[8];
            *(float4*)a        = *(float4*)&As[kk][ty * 4];
            *(float4*)bb       = *(float4*)&Bs[kk][tx * 8];
            *(float4*)(bb + 4) = *(float4*)&Bs[kk][tx * 8 + 4];
#pragma unroll
            for (int i = 0; i < 4; i++)
#pragma unroll
                for (int j = 0; j < 8; j++) acc[i][j] = fmaf(a[i], bb[j], acc[i][j]);
        }
        __syncthreads();
    }
    float* o = d_part + ((size_t)blockIdx.y * Bb) * D;
#pragma unroll
    for (int i = 0; i < 4; i++)
#pragma unroll
        for (int j = 0; j < 8; j++)
            o[(ty * 4 + i) * D + n0 + tx * 8 + j] = acc[i][j];
}

__global__ void k_reduce_q(const float* __restrict__ bq) {
    int idx = blockIdx.x * 256 + threadIdx.x;
    if (idx >= Bb * D) return;
    float s = 0.f;
#pragma unroll
    for (int kz = 0; kz < 32; kz++) s += d_part[(size_t)kz * Bb * D + idx];
    d_query[idx] = s + bq[idx & (D - 1)];
}

// ---------------- base_scores = query @ keys^T * inv_sqrt_d, split-K=4 --------
// grid (128 n-tiles, 4 k-slices of 512), block 256
__global__ void __launch_bounds__(256) k_base(const float* __restrict__ keys) {
    const int n0 = blockIdx.x * 128;
    const int kbase = blockIdx.y * 512;
    __shared__ float As[32][64];
    __shared__ float Bs[32][128];
    const int tid = threadIdx.x;
    const int tx = tid & 15, ty = tid >> 4;
    float acc[4][8];
#pragma unroll
    for (int i = 0; i < 4; i++)
#pragma unroll
        for (int j = 0; j < 8; j++) acc[i][j] = 0.f;

    for (int kc = 0; kc < 512; kc += 32) {
        int k0 = kbase + kc;
#pragma unroll
        for (int j = 0; j < 2; j++) {
            int idx = tid * 2 + j;
            int m = idx >> 3, c4 = idx & 7;
            float4 v = *(const float4*)&d_query[m * D + k0 + c4 * 4];
            As[c4 * 4 + 0][m] = v.x; As[c4 * 4 + 1][m] = v.y;
            As[c4 * 4 + 2][m] = v.z; As[c4 * 4 + 3][m] = v.w;
        }
#pragma unroll
        for (int j = 0; j < 4; j++) {
            int idx = tid * 4 + j;
            int n = idx >> 3, c4 = idx & 7;
            float4 v = *(const float4*)&keys[(size_t)(n0 + n) * D + k0 + c4 * 4];
            Bs[c4 * 4 + 0][n] = v.x; Bs[c4 * 4 + 1][n] = v.y;
            Bs[c4 * 4 + 2][n] = v.z; Bs[c4 * 4 + 3][n] = v.w;
        }
        __syncthreads();
#pragma unroll
        for (int kk = 0; kk < 32; kk++) {
            float a[4], bb[8];
            *(float4*)a        = *(float4*)&As[kk][ty * 4];
            *(float4*)bb       = *(float4*)&Bs[kk][tx * 8];
            *(float4*)(bb + 4) = *(float4*)&Bs[kk][tx * 8 + 4];
#pragma unroll
            for (int i = 0; i < 4; i++)
#pragma unroll
                for (int j = 0; j < 8; j++) acc[i][j] = fmaf(a[i], bb[j], acc[i][j]);
        }
        __syncthreads();
    }
    float* o = d_part + ((size_t)blockIdx.y * Bb) * NBUF;
#pragma unroll
    for (int i = 0; i < 4; i++)
#pragma unroll
        for (int j = 0; j < 8; j++)
            o[(size_t)(ty * 4 + i) * NBUF + n0 + tx * 8 + j] = acc[i][j];
}

__global__ void k_reduce_base() {
    int idx = blockIdx.x * 256 + threadIdx.x;
    const float scale = 0.022097086912079608f;  // 1/sqrt(2048)
    float s = 0.f;
#pragma unroll
    for (int kz = 0; kz < 4; kz++) s += d_part[(size_t)kz * Bb * NBUF + idx];
    d_base[idx] = s * scale;
}

// ---------------- persistent round-loop kernel --------------------------------
__device__ __forceinline__ void gridbar() {
    __syncthreads();
    if (threadIdx.x == 0) {
        __threadfence();
        unsigned g = atomicAdd(&d_bar_gen, 0u);
        if (atomicAdd(&d_bar_cnt, 1u) == GRIDB - 1u) {
            d_bar_cnt = 0u;
            __threadfence();
            atomicAdd(&d_bar_gen, 1u);
        } else {
            while (atomicAdd(&d_bar_gen, 0u) == g) { }
        }
        __threadfence();
    }
    __syncthreads();
}

__global__ void __launch_bounds__(256) k_rounds(const float* __restrict__ prio) {
    const int tid = threadIdx.x;
    const int blk = blockIdx.x;
    __shared__ float red[256];
    __shared__ float invs[64];
    const float DK = -0.105360515657826301f;  // ln(0.9)

    float wsum = 0.f;
    float rw = 1.f;
    for (int r = 0; r < ROUNDS; r++) {
        // ---- Phase A: every block redundantly computes full activeSum (deterministic)
        float s = 0.f;
        for (int n = tid; n < NBUF; n += 256) {
            float w   = __ldcg(&d_wages[n]);
            float eff = prio[n] * __expf(w * DK);
            s += d_validf[n] / (1.f + __expf((0.5f - eff) * 10.f));
        }
        red[tid] = s; __syncthreads();
        for (int off = 128; off > 0; off >>= 1) {
            if (tid < off) red[tid] += red[tid + off];
            __syncthreads();
        }
        float activeSum = red[0];
        __syncthreads();
        if (activeSum < 0.5f) break;   // stopped latches; all future rounds no-op
        wsum += rw;

        // ---- Phase B: rowsum partials. 2 blocks per b-row.
        {
            int b  = blk >> 1;
            int n0 = (blk & 1) * (NBUF / 2);
            const float* br = d_base + (size_t)b * NBUF + n0;
            float ps = 0.f;
            for (int i = tid; i < NBUF / 2; i += 256) {
                int n = n0 + i;
                float w   = __ldcg(&d_wages[n]);
                float eff = prio[n] * __expf(w * DK);
                float vf  = d_validf[n];
                float g   = eff * vf / (1.f + __expf((0.5f - eff) * 10.f));
                float e   = (vf != 0.f) ? __expf(br[i] * g) : 0.f;
                ps += e;
            }
            red[tid] = ps; __syncthreads();
            for (int off = 128; off > 0; off >>= 1) {
                if (tid < off) red[tid] += red[tid + off];
                __syncthreads();
            }
            if (tid == 0) __stcg(&d_rs_part[(blk & 1) * Bb + b], red[0]);
        }
        gridbar();

        // ---- Phase C: AW += rw*aw ; wages += colmean(aw). 128 cols/block.
        {
            if (tid < 64)
                invs[tid] = 1.f / (__ldcg(&d_rs_part[tid]) + __ldcg(&d_rs_part[Bb + tid]));
            __syncthreads();
            int col = blk * 128 + (tid & 127);
            int blo = (tid >> 7) * 32;
            float w   = __ldcg(&d_wages[col]);
            float eff = prio[col] * __expf(w * DK);
            float vf  = d_validf[col];
            float g   = eff * vf / (1.f + __expf((0.5f - eff) * 10.f));
            float vz  = (vf != 0.f) ? 1.f : 0.f;
            float cs = 0.f;
#pragma unroll 8
            for (int bb = blo; bb < blo + 32; bb++) {
                size_t idx = (size_t)bb * NBUF + col;
                float e = vz * __expf(d_base[idx] * g) * invs[bb];
                d_AW[idx] += rw * e;
                cs += e;
            }
            __syncthreads();
            red[tid] = cs; __syncthreads();
            if (tid < 128) {
                float c = red[tid] + red[tid + 128];
                __stcg(&d_wages[col], w + c * (1.f / 64.f));
            }
        }
        gridbar();
        rw *= 0.9f;
    }
    if (blk == 0 && tid == 0) d_wsum = wsum;
}

// ---------------- C1 = AW @ values, split-N=32 (slices of 512) ----------------
// grid (16 d-tiles, 32 n-slices), block 256, tile 64x128
__global__ void __launch_bounds__(256) k_av(const float* __restrict__ V) {
    const int d0 = blockIdx.x * 128;
    const int nbase = blockIdx.y * 512;
    __shared__ float As[32][64];
    __shared__ float Bs[32][128];
    const int tid = threadIdx.x;
    const int tx = tid & 15, ty = tid >> 4;
    float acc[4][8];
#pragma unroll
    for (int i = 0; i < 4; i++)
#pragma unroll
        for (int j = 0; j < 8; j++) acc[i][j] = 0.f;

    for (int nc = 0; nc < 512; nc += 32) {
        int n0 = nbase + nc;
#pragma unroll
        for (int j = 0; j < 2; j++) {
            int idx = tid * 2 + j;
            int m = idx >> 3, c4 = idx & 7;
            float4 v = *(const float4*)&d_AW[(size_t)m * NBUF + n0 + c4 * 4];
            As[c4 * 4 + 0][m] = v.x; As[c4 * 4 + 1][m] = v.y;
            As[c4 * 4 + 2][m] = v.z; As[c4 * 4 + 3][m] = v.w;
        }
#pragma unroll
        for (int j = 0; j < 4; j++) {
            int idx = tid * 4 + j;
            int nl = idx >> 5, d4 = idx & 31;
            *(float4*)&Bs[nl][d4 * 4] =
                *(const float4*)&V[(size_t)(n0 + nl) * D + d0 + d4 * 4];
        }
        __syncthreads();
#pragma unroll
        for (int kk = 0; kk < 32; kk++) {
            float a[4], bb[8];
            *(float4*)a        = *(float4*)&As[kk][ty * 4];
            *(float4*)bb       = *(float4*)&Bs[kk][tx * 8];
            *(float4*)(bb + 4) = *(float4*)&Bs[kk][tx * 8 + 4];
#pragma unroll
            for (int i = 0; i < 4; i++)
#pragma unroll
                for (int j = 0; j < 8; j++) acc[i][j] = fmaf(a[i], bb[j], acc[i][j]);
        }
        __syncthreads();
    }
    float* o = d_part + ((size_t)blockIdx.y * Bb) * D;
#pragma unroll
    for (int i = 0; i < 4; i++)
#pragma unroll
        for (int j = 0; j < 8; j++)
            o[(ty * 4 + i) * D + d0 + tx * 8 + j] = acc[i][j];
}

__global__ void k_reduce_c1() {
    int idx = blockIdx.x * 256 + threadIdx.x;
    if (idx >= Bb * D) return;
    float s = 0.f;
#pragma unroll
    for (int kz = 0; kz < 32; kz++) s += d_part[(size_t)kz * Bb * D + idx];
    d_C1[idx] = s;
}

__global__ void k_reduce_out(const float* __restrict__ bc, float* __restrict__ out) {
    int idx = blockIdx.x * 256 + threadIdx.x;
    if (idx >= Bb * D) return;
    float ws = d_wsum;
    if (ws > 0.f) {
        float s = 0.f;
#pragma unroll
        for (int kz = 0; kz < 32; kz++) s += d_part[(size_t)kz * Bb * D + idx];
        out[idx] = s / fmaxf(ws, 1e-8f) + bc[idx & (D - 1)];
    } else {
        out[idx] = 0.f;
    }
}

// ---------------- launch ------------------------------------------------------
extern "C" void kernel_launch(void* const* d_in, const int* in_sizes, int n_in,
                              void* d_out, int out_size) {
    const float* qs     = (const float*)d_in[0];
    const float* amask  = (const float*)d_in[1];
    const float* keys   = (const float*)d_in[2];
    const float* values = (const float*)d_in[3];
    const float* prio   = (const float*)d_in[4];
    const float* ages   = (const float*)d_in[5];
    const void*  vmask  = d_in[6];
    const float* Wq     = (const float*)d_in[7];
    const float* bq     = (const float*)d_in[8];
    const float* Wc     = (const float*)d_in[9];
    const float* bc     = (const float*)d_in[10];
    float* out = (float*)d_out;

    k_detect<<<1, 256>>>(vmask);
    k_init<<<(Bb * NBUF + 255) / 256, 256>>>(ages);
    k_pool<<<dim3(8, 64), 256>>>(qs, amask);
    k_proj<<<dim3(16, 32), 256>>>(Wq, 0);
    k_reduce_q<<<(Bb * D + 255) / 256, 256>>>(bq);
    k_base<<<dim3(128, 4), 256>>>(keys);
    k_reduce_base<<<(Bb * NBUF) / 256, 256>>>();

    k_rounds<<<GRIDB, 256>>>(prio);

    k_av<<<dim3(16, 32), 256>>>(values);
    k_reduce_c1<<<(Bb * D + 255) / 256, 256>>>();
    k_proj<<<dim3(16, 32), 256>>>(Wc, 1);
    k_reduce_out<<<(Bb * D + 255) / 256, 256>>>(bc, out);
}

// round 8
// speedup vs baseline: 1.5079x; 1.4486x over previous
#include <cuda_runtime.h>
#include <cuda_bf16.h>
#include <math.h>
#include <stdint.h>

#define Bb      64
#define T       512
#define D       2048
#define NBUF    16384
#define ROUNDS  10
#define GRIDB   128
#define PAD     40

// ---------------- scratch (static device globals; no allocation) -------------
// RULE: these symbols are ONLY referenced inside __global__ code, never passed
// as launch arguments from host (host-side symbol address is UB; on GB300/ATS
// it silently aliases CPU memory instead of faulting).
__device__ float d_pooled[Bb * D];
__device__ float d_query[Bb * D];
__device__ float d_base[Bb * NBUF];
__device__ float d_AW[Bb * NBUF];
__device__ float d_validf[NBUF];
__device__ float d_g[NBUF];
__device__ float d_rs_part[2 * Bb];
__device__ float d_active[ROUNDS + 1];
__device__ float d_C1[Bb * D];
__device__ float d_part[4 * Bb * NBUF];   // 16.8 MB split-K partials
__device__ float d_wsum;
__device__ int   d_flag0;                 // TRANSB=0 mma verdict (1 = bad)
__device__ int   d_flag1;                 // TRANSB=1 mma verdict
__device__ unsigned d_bar_cnt;
__device__ unsigned d_bar_gen;

// ---------------- mma helpers -------------------------------------------------
__device__ __forceinline__ void mma16816(float* c, const uint32_t* a,
                                         uint32_t b0, uint32_t b1) {
    asm volatile("mma.sync.aligned.m16n8k16.row.col.f32.bf16.bf16.f32 "
                 "{%0,%1,%2,%3}, {%4,%5,%6,%7}, {%8,%9}, {%0,%1,%2,%3};"
                 : "+f"(c[0]), "+f"(c[1]), "+f"(c[2]), "+f"(c[3])
                 : "r"(a[0]), "r"(a[1]), "r"(a[2]), "r"(a[3]), "r"(b0), "r"(b1));
}
__device__ __forceinline__ uint32_t pack2(__nv_bfloat16 a, __nv_bfloat16 b) {
    return ((uint32_t)__bfloat16_as_ushort(b) << 16) | __bfloat16_as_ushort(a);
}
__device__ __forceinline__ void split4(float4 v, uint2& H, uint2& L) {
    __nv_bfloat16 hx = __float2bfloat16(v.x), hy = __float2bfloat16(v.y);
    __nv_bfloat16 hz = __float2bfloat16(v.z), hw = __float2bfloat16(v.w);
    __nv_bfloat16 lx = __float2bfloat16(v.x - __bfloat162float(hx));
    __nv_bfloat16 ly = __float2bfloat16(v.y - __bfloat162float(hy));
    __nv_bfloat16 lz = __float2bfloat16(v.z - __bfloat162float(hz));
    __nv_bfloat16 lw = __float2bfloat16(v.w - __bfloat162float(hw));
    H.x = pack2(hx, hy); H.y = pack2(hz, hw);
    L.x = pack2(lx, ly); L.y = pack2(lz, lw);
}
// packed fp32x2 (base-ISA FFMA2) for the fallback
__device__ __forceinline__ double pack_dup(float a) {
    double r; asm("mov.b64 %0, {%1, %1};" : "=d"(r) : "f"(a)); return r;
}
__device__ __forceinline__ void fma2(double& acc, double a, double b) {
    asm("fma.rn.f32x2 %0, %1, %2, %0;" : "+d"(acc) : "d"(a), "d"(b));
}
__device__ __forceinline__ void unpack2(double v, float& lo, float& hi) {
    asm("mov.b64 {%0, %1}, %2;" : "=f"(lo), "=f"(hi) : "d"(v));
}

// ---------------- MODE table ---------------------------------------------------
// 0: d_part <- d_pooled @ B^T          (B=Wq,    Ntot=D,    Kslice=128, grid 16x16)
// 1: d_part <- d_query  @ B^T          (B=keys,  Ntot=NBUF, Kslice=512, grid 128x4)
// 2: d_part <- d_AW     @ B (row-ctr)  (B=values,Ntot=D,    Kslice=512, grid 16x32)
// 3: d_part <- d_C1     @ B^T          (B=Wc,    Ntot=D,    Kslice=128, grid 16x16)
template<int MODE> __device__ __forceinline__ const float* mmA() {
    if (MODE == 0) return d_pooled;
    if (MODE == 1) return d_query;
    if (MODE == 2) return d_AW;
    return d_C1;
}
template<int MODE> struct MM {
    static const int TRANSB = (MODE == 2) ? 1 : 0;
    static const int LDA    = (MODE == 2) ? NBUF : D;
    static const int NTOT   = (MODE == 1) ? NBUF : D;
    static const int KSL    = (MODE == 0 || MODE == 3) ? 128 : 512;
};

// ---------------- split-precision bf16 mma GEMM -------------------------------
template<int MODE>
__global__ void __launch_bounds__(256) k_mm(const float* __restrict__ B, int ldb) {
    const int TRANSB = MM<MODE>::TRANSB;
    const int lda = MM<MODE>::LDA, Ntot = MM<MODE>::NTOT, Kslice = MM<MODE>::KSL;
    const float* __restrict__ A = mmA<MODE>();
    __shared__ __align__(16) __nv_bfloat16 sAhi[64 * PAD], sAlo[64 * PAD];
    __shared__ __align__(16) __nv_bfloat16 sBhi[128 * PAD], sBlo[128 * PAD];
    const int tid = threadIdx.x, lane = tid & 31, w = tid >> 5;
    const int wm = w >> 2, wn = w & 3;
    const int g = lane >> 2, t2 = (lane & 3) * 2;
    const int n0 = blockIdx.x * 128;
    const int kbase = blockIdx.y * Kslice;

    float acc[2][4][4];
#pragma unroll
    for (int f = 0; f < 2; f++)
#pragma unroll
        for (int q = 0; q < 4; q++)
#pragma unroll
            for (int i = 0; i < 4; i++) acc[f][q][i] = 0.f;

    for (int kc = 0; kc < Kslice; kc += 32) {
        const int k0 = kbase + kc;
        __syncthreads();
        for (int i = tid; i < 512; i += 256) {
            int r = i >> 3, c4 = (i & 7) * 4;
            float4 v = *(const float4*)&A[(size_t)r * lda + k0 + c4];
            uint2 H, L; split4(v, H, L);
            *(uint2*)&sAhi[r * PAD + c4] = H;
            *(uint2*)&sAlo[r * PAD + c4] = L;
        }
        if (!TRANSB) {
            for (int i = tid; i < 1024; i += 256) {
                int r = i >> 3, c4 = (i & 7) * 4;
                float4 v = *(const float4*)&B[(size_t)(n0 + r) * ldb + k0 + c4];
                uint2 H, L; split4(v, H, L);
                *(uint2*)&sBhi[r * PAD + c4] = H;
                *(uint2*)&sBlo[r * PAD + c4] = L;
            }
        } else {
            int cc = tid & 127, rb = (tid >> 7) * 4;
#pragma unroll
            for (int it = 0; it < 4; it++) {
                int rr = rb + it * 8;
                float4 v;
                v.x = B[(size_t)(k0 + rr + 0) * ldb + n0 + cc];
                v.y = B[(size_t)(k0 + rr + 1) * ldb + n0 + cc];
                v.z = B[(size_t)(k0 + rr + 2) * ldb + n0 + cc];
                v.w = B[(size_t)(k0 + rr + 3) * ldb + n0 + cc];
                uint2 H, L; split4(v, H, L);
                *(uint2*)&sBhi[cc * PAD + rr] = H;
                *(uint2*)&sBlo[cc * PAD + rr] = L;
            }
        }
        __syncthreads();
#pragma unroll
        for (int ks = 0; ks < 32; ks += 16) {
            const int cA = ks + t2;
            uint32_t ahi[2][4], alo[2][4];
#pragma unroll
            for (int f = 0; f < 2; f++) {
                int ra = wm * 32 + f * 16 + g;
                ahi[f][0] = *(const uint32_t*)&sAhi[ra * PAD + cA];
                ahi[f][1] = *(const uint32_t*)&sAhi[(ra + 8) * PAD + cA];
                ahi[f][2] = *(const uint32_t*)&sAhi[ra * PAD + cA + 8];
                ahi[f][3] = *(const uint32_t*)&sAhi[(ra + 8) * PAD + cA + 8];
                alo[f][0] = *(const uint32_t*)&sAlo[ra * PAD + cA];
                alo[f][1] = *(const uint32_t*)&sAlo[(ra + 8) * PAD + cA];
                alo[f][2] = *(const uint32_t*)&sAlo[ra * PAD + cA + 8];
                alo[f][3] = *(const uint32_t*)&sAlo[(ra + 8) * PAD + cA + 8];
            }
#pragma unroll
            for (int nb = 0; nb < 4; nb++) {
                int nc = wn * 32 + nb * 8 + g;
                uint32_t bh0 = *(const uint32_t*)&sBhi[nc * PAD + cA];
                uint32_t bh1 = *(const uint32_t*)&sBhi[nc * PAD + cA + 8];
                uint32_t bl0 = *(const uint32_t*)&sBlo[nc * PAD + cA];
                uint32_t bl1 = *(const uint32_t*)&sBlo[nc * PAD + cA + 8];
#pragma unroll
                for (int f = 0; f < 2; f++) {
                    mma16816(acc[f][nb], ahi[f], bh0, bh1);
                    mma16816(acc[f][nb], ahi[f], bl0, bl1);
                    mma16816(acc[f][nb], alo[f], bh0, bh1);
                }
            }
        }
    }
    float* Cp = d_part + (size_t)blockIdx.y * 64 * Ntot;
    int r0 = wm * 32 + g;
#pragma unroll
    for (int f = 0; f < 2; f++)
#pragma unroll
        for (int nb = 0; nb < 4; nb++) {
            int rr = r0 + f * 16;
            int col = n0 + wn * 32 + nb * 8 + t2;
            *(float2*)&Cp[(size_t)rr * Ntot + col] =
                make_float2(acc[f][nb][0], acc[f][nb][1]);
            *(float2*)&Cp[(size_t)(rr + 8) * Ntot + col] =
                make_float2(acc[f][nb][2], acc[f][nb][3]);
        }
}

// ---------------- fp32 sample check (64 entries, warp each) -------------------
// CHK 0: d_query vs d_pooled@Wq^T + bq      -> d_flag0
// CHK 1: d_C1    vs d_AW@values (row-ctr)   -> d_flag1
template<int CHK>
__global__ void k_check(const float* __restrict__ B, int ldb,
                        const float* __restrict__ bias) {
    const float* __restrict__ A   = (CHK == 0) ? d_pooled : d_AW;
    const float* __restrict__ Cc  = (CHK == 0) ? d_query : d_C1;
    const int lda = (CHK == 0) ? D : NBUF;
    const int K   = (CHK == 0) ? D : NBUF;
    int gw = (blockIdx.x * blockDim.x + threadIdx.x) >> 5;
    int lane = threadIdx.x & 31;
    int row = (gw * 37) & 63;
    int col = (int)((gw * 2654435761u) % (unsigned)D);
    float s = 0.f;
    if (CHK == 0) {
        for (int k = lane; k < K; k += 32)
            s += A[(size_t)row * lda + k] * B[(size_t)col * ldb + k];
    } else {
        for (int k = lane; k < K; k += 32)
            s += A[(size_t)row * lda + k] * B[(size_t)k * ldb + col];
    }
#pragma unroll
    for (int o = 16; o; o >>= 1) s += __shfl_xor_sync(0xFFFFFFFFu, s, o);
    if (lane == 0) {
        float ref = s + (bias ? bias[col] : 0.f);
        float got = Cc[(size_t)row * D + col];
        float tol = 0.02f * fabsf(ref) + 1e-3f;
        if (!(fabsf(got - ref) <= tol)) {
            if (CHK == 0) atomicExch(&d_flag0, 1);
            else          atomicExch(&d_flag1, 1);
        }
    }
}

// ---------------- f32x2 fallback GEMM (flag-gated, full recompute) ------------
// FM 0: d_query = d_pooled@Wq^T + bq            (flag0, grid 16)
// FM 1: d_base  = d_query@keys^T * SC           (flag0, grid 128)
// FM 2: d_C1    = d_AW@values                   (flag1, grid 16)
// FM 3: out     = (d_C1@Wc^T)/wsum + bc         (flag0, grid 16)
template<int FM>
__global__ void __launch_bounds__(256) k_fp(const float* __restrict__ B, int ldb,
                                            const float* __restrict__ bias,
                                            float* __restrict__ outp) {
    if (((FM == 2) ? d_flag1 : d_flag0) == 0) return;
    const float* __restrict__ A = (FM == 0) ? d_pooled : (FM == 1) ? d_query
                                 : (FM == 2) ? d_AW : d_C1;
    float* __restrict__ Cout = (FM == 0) ? d_query : (FM == 1) ? d_base
                               : (FM == 2) ? d_C1 : outp;
    const int lda  = (FM == 2) ? NBUF : D;
    const int K    = (FM == 2) ? NBUF : D;
    const int Ntot = (FM == 1) ? NBUF : D;
    const int TRANSB = (FM == 2) ? 1 : 0;
    const float scale = (FM == 1) ? 0.022097086912079608f : 1.0f;

    __shared__ float As[32][64];
    __shared__ float Bs[32][128];
    const int tid = threadIdx.x, tx = tid & 15, ty = tid >> 4;
    const int n0 = blockIdx.x * 128;
    double acc[4][4];
#pragma unroll
    for (int i = 0; i < 4; i++)
#pragma unroll
        for (int j = 0; j < 4; j++) acc[i][j] = 0.0;

    for (int k0 = 0; k0 < K; k0 += 32) {
#pragma unroll
        for (int j = 0; j < 2; j++) {
            int idx = tid * 2 + j, m = idx >> 3, c4 = idx & 7;
            float4 v = *(const float4*)&A[(size_t)m * lda + k0 + c4 * 4];
            As[c4 * 4 + 0][m] = v.x; As[c4 * 4 + 1][m] = v.y;
            As[c4 * 4 + 2][m] = v.z; As[c4 * 4 + 3][m] = v.w;
        }
        if (!TRANSB) {
#pragma unroll
            for (int j = 0; j < 4; j++) {
                int idx = tid * 4 + j, n = idx >> 3, c4 = idx & 7;
                float4 v = *(const float4*)&B[(size_t)(n0 + n) * ldb + k0 + c4 * 4];
                Bs[c4 * 4 + 0][n] = v.x; Bs[c4 * 4 + 1][n] = v.y;
                Bs[c4 * 4 + 2][n] = v.z; Bs[c4 * 4 + 3][n] = v.w;
            }
        } else {
#pragma unroll
            for (int j = 0; j < 4; j++) {
                int idx = tid * 4 + j, kk = idx >> 5, n4 = idx & 31;
                *(float4*)&Bs[kk][n4 * 4] =
                    *(const float4*)&B[(size_t)(k0 + kk) * ldb + n0 + n4 * 4];
            }
        }
        __syncthreads();
#pragma unroll 8
        for (int kk = 0; kk < 32; kk++) {
            float4 av = *(const float4*)&As[kk][ty * 4];
            double2 b01 = *(const double2*)&Bs[kk][tx * 8];
            double2 b23 = *(const double2*)&Bs[kk][tx * 8 + 4];
            double a0 = pack_dup(av.x), a1 = pack_dup(av.y);
            double a2 = pack_dup(av.z), a3 = pack_dup(av.w);
            fma2(acc[0][0], a0, b01.x); fma2(acc[0][1], a0, b01.y);
            fma2(acc[0][2], a0, b23.x); fma2(acc[0][3], a0, b23.y);
            fma2(acc[1][0], a1, b01.x); fma2(acc[1][1], a1, b01.y);
            fma2(acc[1][2], a1, b23.x); fma2(acc[1][3], a1, b23.y);
            fma2(acc[2][0], a2, b01.x); fma2(acc[2][1], a2, b01.y);
            fma2(acc[2][2], a2, b23.x); fma2(acc[2][3], a2, b23.y);
            fma2(acc[3][0], a3, b01.x); fma2(acc[3][1], a3, b01.y);
            fma2(acc[3][2], a3, b23.x); fma2(acc[3][3], a3, b23.y);
        }
        __syncthreads();
    }
    float ws = d_wsum;
#pragma unroll
    for (int i = 0; i < 4; i++) {
        int row = ty * 4 + i;
        float o[8];
        unpack2(acc[i][0], o[0], o[1]); unpack2(acc[i][1], o[2], o[3]);
        unpack2(acc[i][2], o[4], o[5]); unpack2(acc[i][3], o[6], o[7]);
#pragma unroll
        for (int j = 0; j < 8; j++) {
            int col = n0 + tx * 8 + j;
            float c = o[j] * scale;
            if (FM == 3)       c = (ws > 0.f) ? c / fmaxf(ws, 1e-8f) + bias[col] : 0.f;
            else if (FM == 0)  c += bias[col];
            Cout[(size_t)row * Ntot + col] = c;
        }
    }
}

// ---------------- valid_mask dtype detection + conversion --------------------
__global__ void k_detect(const void* vm) {
    __shared__ int mode;
    if (threadIdx.x == 0) {
        const float* fp = (const float*)vm;
        const int*   ip = (const int*)vm;
        bool isF = true, isI = true;
        for (int k = 0; k < 64; k++) {
            float f = fp[k];
            if (!(f == 0.0f || f == 1.0f)) isF = false;
            int v = ip[k];
            if (!(v == 0 || v == 1)) isI = false;
        }
        mode = isF ? 2 : (isI ? 1 : 0);
    }
    __syncthreads();
    int m = mode;
    const unsigned char* cp = (const unsigned char*)vm;
    const int*   ip = (const int*)vm;
    const float* fp = (const float*)vm;
    for (int n = threadIdx.x; n < NBUF; n += blockDim.x) {
        float v;
        if (m == 2)      v = (fp[n] != 0.0f) ? 1.f : 0.f;
        else if (m == 1) v = (ip[n] != 0)    ? 1.f : 0.f;
        else             v = (cp[n] != 0)    ? 1.f : 0.f;
        d_validf[n] = v;
    }
}

__global__ void k_init() {
    int i = blockIdx.x * 256 + threadIdx.x;
    if (i < Bb * NBUF) d_AW[i] = 0.f;
    if (i <= ROUNDS)   d_active[i] = 0.f;
    if (i == 0) { d_wsum = 0.f; d_flag0 = 0; d_flag1 = 0; }
}

// ---------------- masked mean pool -------------------------------------------
__global__ void __launch_bounds__(256) k_pool(const float* __restrict__ qs,
                                              const float* __restrict__ mask) {
    int b = blockIdx.y;
    int d = blockIdx.x * 256 + threadIdx.x;
    __shared__ float sm[T];
    __shared__ float red[256];
    for (int t = threadIdx.x; t < T; t += 256) sm[t] = mask[b * T + t];
    __syncthreads();
    red[threadIdx.x] = sm[threadIdx.x] + sm[threadIdx.x + 256];
    __syncthreads();
    for (int off = 128; off > 0; off >>= 1) {
        if (threadIdx.x < off) red[threadIdx.x] += red[threadIdx.x + off];
        __syncthreads();
    }
    float msum = red[0];
    const float* base = qs + ((size_t)b * T) * D + d;
    float a0 = 0, a1 = 0, a2 = 0, a3 = 0;
    for (int t = 0; t < T; t += 4) {
        a0 += base[(size_t)(t + 0) * D] * sm[t + 0];
        a1 += base[(size_t)(t + 1) * D] * sm[t + 1];
        a2 += base[(size_t)(t + 2) * D] * sm[t + 2];
        a3 += base[(size_t)(t + 3) * D] * sm[t + 3];
    }
    d_pooled[b * D + d] = (a0 + a1 + a2 + a3) / (msum + 1e-8f);
}

// ---------------- split-K reduces ---------------------------------------------
__global__ void k_reduce_q(const float* __restrict__ bq) {
    int idx = blockIdx.x * 256 + threadIdx.x;
    if (idx >= Bb * D) return;
    float s = 0.f;
#pragma unroll
    for (int kz = 0; kz < 16; kz++) s += d_part[(size_t)kz * Bb * D + idx];
    d_query[idx] = s + bq[idx & (D - 1)];
}

__global__ void k_reduce_base() {
    int idx = blockIdx.x * 256 + threadIdx.x;
    float s = 0.f;
#pragma unroll
    for (int kz = 0; kz < 4; kz++) s += d_part[(size_t)kz * Bb * NBUF + idx];
    d_base[idx] = s * 0.022097086912079608f;
}

__global__ void k_reduce_c1() {
    int idx = blockIdx.x * 256 + threadIdx.x;
    if (idx >= Bb * D) return;
    float s = 0.f;
#pragma unroll
    for (int kz = 0; kz < 32; kz++) s += d_part[(size_t)kz * Bb * D + idx];
    d_C1[idx] = s;
}

__global__ void k_reduce_out(const float* __restrict__ bc, float* __restrict__ out) {
    int idx = blockIdx.x * 256 + threadIdx.x;
    if (idx >= Bb * D) return;
    float ws = d_wsum;
    if (ws > 0.f) {
        float s = 0.f;
#pragma unroll
        for (int kz = 0; kz < 16; kz++) s += d_part[(size_t)kz * Bb * D + idx];
        out[idx] = s / fmaxf(ws, 1e-8f) + bc[idx & (D - 1)];
    } else {
        out[idx] = 0.f;
    }
}

// ---------------- persistent round-loop kernel --------------------------------
__device__ __forceinline__ void gridbar() {
    __syncthreads();
    if (threadIdx.x == 0) {
        __threadfence();
        unsigned g = atomicAdd(&d_bar_gen, 0u);
        if (atomicAdd(&d_bar_cnt, 1u) == GRIDB - 1u) {
            d_bar_cnt = 0u;
            __threadfence();
            atomicAdd(&d_bar_gen, 1u);
        } else {
            while (atomicAdd(&d_bar_gen, 0u) == g) { }
        }
        __threadfence();
    }
    __syncthreads();
}

__global__ void __launch_bounds__(256) k_rounds(const float* __restrict__ prio,
                                                const float* __restrict__ ages) {
    const int tid = threadIdx.x, blk = blockIdx.x;
    __shared__ float red[256];
    __shared__ float invs[64];
    const float DK = -0.105360515657826301f;  // ln(0.9)
    const int col = blk * 128 + (tid & 127);
    const int half = tid >> 7;

    float w  = ages[col];
    float p  = prio[col];
    float vf = d_validf[col];

    // prologue: g(0) + active(0)
    {
        float a = 0.f;
        if (tid < 128) {
            float eff = p * __expf(w * DK);
            float act = vf / (1.f + __expf((0.5f - eff) * 10.f));
            __stcg(&d_g[col], act * eff);
            a = act;
        }
        red[tid] = a; __syncthreads();
        for (int off = 128; off; off >>= 1) {
            if (tid < off) red[tid] += red[tid + off];
            __syncthreads();
        }
        if (tid == 0) atomicAdd(&d_active[0], red[0]);
    }
    gridbar();

    float wsum = 0.f, rw = 1.f;
    for (int r = 0; r < ROUNDS; r++) {
        if (__ldcg(&d_active[r]) < 0.5f) break;
        wsum += rw;

        // ---- Phase B: rowsum partials (2 blocks per batch row)
        {
            int b   = blk >> 1;
            int n0b = (blk & 1) * (NBUF / 2);
            const float* br = d_base + (size_t)b * NBUF + n0b;
            float ps = 0.f;
            for (int i = tid; i < NBUF / 2; i += 256) {
                int n = n0b + i;
                ps += d_validf[n] * __expf(br[i] * __ldcg(&d_g[n]));
            }
            red[tid] = ps; __syncthreads();
            for (int off = 128; off; off >>= 1) {
                if (tid < off) red[tid] += red[tid + off];
                __syncthreads();
            }
            if (tid == 0) __stcg(&d_rs_part[(blk & 1) * Bb + b], red[0]);
        }
        gridbar();

        // ---- Phase C: AW += rw*aw ; wages += colmean ; g(r+1), active(r+1)
        {
            if (tid < 64)
                invs[tid] = 1.f / (__ldcg(&d_rs_part[tid]) + __ldcg(&d_rs_part[Bb + tid]));
            __syncthreads();
            float g = __ldcg(&d_g[col]);
            float cs = 0.f;
            int blo = half * 32;
#pragma unroll 8
            for (int bb = blo; bb < blo + 32; bb++) {
                size_t idx = (size_t)bb * NBUF + col;
                float e = vf * __expf(d_base[idx] * g) * invs[bb];
                d_AW[idx] += rw * e;
                cs += e;
            }
            __syncthreads();
            red[tid] = cs; __syncthreads();
            float act = 0.f;
            if (tid < 128) {
                w += (red[tid] + red[tid + 128]) * (1.f / 64.f);
                float eff = p * __expf(w * DK);
                act = vf / (1.f + __expf((0.5f - eff) * 10.f));
                __stcg(&d_g[col], act * eff);
            }
            __syncthreads();
            red[tid] = act; __syncthreads();
            for (int off = 128; off; off >>= 1) {
                if (tid < off) red[tid] += red[tid + off];
                __syncthreads();
            }
            if (tid == 0) atomicAdd(&d_active[r + 1], red[0]);
        }
        gridbar();
        rw *= 0.9f;
    }
    if (blk == 0 && tid == 0) d_wsum = wsum;
}

// ---------------- launch ------------------------------------------------------
extern "C" void kernel_launch(void* const* d_in, const int* in_sizes, int n_in,
                              void* d_out, int out_size) {
    const float* qs     = (const float*)d_in[0];
    const float* amask  = (const float*)d_in[1];
    const float* keys   = (const float*)d_in[2];
    const float* values = (const float*)d_in[3];
    const float* prio   = (const float*)d_in[4];
    const float* ages   = (const float*)d_in[5];
    const void*  vmask  = d_in[6];
    const float* Wq     = (const float*)d_in[7];
    const float* bq     = (const float*)d_in[8];
    const float* Wc     = (const float*)d_in[9];
    const float* bc     = (const float*)d_in[10];
    float* out = (float*)d_out;

    k_detect<<<1, 256>>>(vmask);
    k_init<<<(Bb * NBUF + 255) / 256, 256>>>();
    k_pool<<<dim3(8, 64), 256>>>(qs, amask);

    // query = pooled @ Wq^T + bq  (mma split-K=16; checked; f32x2 fallback)
    k_mm<0><<<dim3(16, 16), 256>>>(Wq, D);
    k_reduce_q<<<(Bb * D + 255) / 256, 256>>>(bq);
    k_check<0><<<8, 256>>>(Wq, D, bq);
    k_fp<0><<<16, 256>>>(Wq, D, bq, (float*)0);

    // base = query @ keys^T * SC  (mma split-K=4; gated by same flag0)
    k_mm<1><<<dim3(128, 4), 256>>>(keys, D);
    k_reduce_base<<<(Bb * NBUF) / 256, 256>>>();
    k_fp<1><<<128, 256>>>(keys, D, (const float*)0, (float*)0);

    k_rounds<<<GRIDB, 256>>>(prio, ages);

    // C1 = AW @ values  (mma split-K=32; checked; fallback)
    k_mm<2><<<dim3(16, 32), 256>>>(values, D);
    k_reduce_c1<<<(Bb * D + 255) / 256, 256>>>();
    k_check<1><<<8, 256>>>(values, D, (const float*)0);
    k_fp<2><<<16, 256>>>(values, D, (const float*)0, (float*)0);

    // out = (C1 @ Wc^T)/wsum + bc
    k_mm<3><<<dim3(16, 16), 256>>>(Wc, D);
    k_reduce_out<<<(Bb * D + 255) / 256, 256>>>(bc, out);
    k_fp<3><<<16, 256>>>(Wc, D, bc, out);
}

// round 9
// speedup vs baseline: 1.9542x; 1.2959x over previous
#include <cuda_runtime.h>
#include <cuda_bf16.h>
#include <math.h>
#include <stdint.h>

#define Bb      64
#define T       512
#define D       2048
#define NBUF    16384
#define ROUNDS  10
#define GRIDB   128
#define PAD     40
#define SMEM_MM (1536 * PAD)   // bytes: 2 bufs x (A hi/lo 64*PAD + B hi/lo 128*PAD) bf16

// ---------------- scratch (static device globals; no allocation) -------------
// RULE: device symbols are ONLY referenced inside __global__ code, never passed
// as launch arguments (host symbol address + GB300 ATS = silent host aliasing).
__device__ float d_pooled[Bb * D];
__device__ float d_query[Bb * D];
__device__ float d_base[Bb * NBUF];
__device__ float d_AW[Bb * NBUF];
__device__ float d_validf[NBUF];
__device__ float d_g[NBUF];
__device__ float d_rs_part[2 * Bb];
__device__ float d_active[ROUNDS + 1];
__device__ float d_C1[Bb * D];
__device__ float d_part[4 * Bb * NBUF];   // split-K partials; E-buffer during rounds
__device__ float d_wsum;
__device__ int   d_flag0;
__device__ int   d_flag1;
__device__ unsigned d_bar_cnt;
__device__ unsigned d_bar_gen;

// ---------------- mma helpers -------------------------------------------------
__device__ __forceinline__ void mma16816(float* c, const uint32_t* a,
                                         uint32_t b0, uint32_t b1) {
    asm volatile("mma.sync.aligned.m16n8k16.row.col.f32.bf16.bf16.f32 "
                 "{%0,%1,%2,%3}, {%4,%5,%6,%7}, {%8,%9}, {%0,%1,%2,%3};"
                 : "+f"(c[0]), "+f"(c[1]), "+f"(c[2]), "+f"(c[3])
                 : "r"(a[0]), "r"(a[1]), "r"(a[2]), "r"(a[3]), "r"(b0), "r"(b1));
}
__device__ __forceinline__ uint32_t pack2(__nv_bfloat16 a, __nv_bfloat16 b) {
    return ((uint32_t)__bfloat16_as_ushort(b) << 16) | __bfloat16_as_ushort(a);
}
__device__ __forceinline__ void split4(float4 v, uint2& H, uint2& L) {
    __nv_bfloat16 hx = __float2bfloat16(v.x), hy = __float2bfloat16(v.y);
    __nv_bfloat16 hz = __float2bfloat16(v.z), hw = __float2bfloat16(v.w);
    __nv_bfloat16 lx = __float2bfloat16(v.x - __bfloat162float(hx));
    __nv_bfloat16 ly = __float2bfloat16(v.y - __bfloat162float(hy));
    __nv_bfloat16 lz = __float2bfloat16(v.z - __bfloat162float(hz));
    __nv_bfloat16 lw = __float2bfloat16(v.w - __bfloat162float(hw));
    H.x = pack2(hx, hy); H.y = pack2(hz, hw);
    L.x = pack2(lx, ly); L.y = pack2(lz, lw);
}
__device__ __forceinline__ double pack_dup(float a) {
    double r; asm("mov.b64 %0, {%1, %1};" : "=d"(r) : "f"(a)); return r;
}
__device__ __forceinline__ void fma2(double& acc, double a, double b) {
    asm("fma.rn.f32x2 %0, %1, %2, %0;" : "+d"(acc) : "d"(a), "d"(b));
}
__device__ __forceinline__ void unpack2(double v, float& lo, float& hi) {
    asm("mov.b64 {%0, %1}, %2;" : "=f"(lo), "=f"(hi) : "d"(v));
}

// ---------------- MODE table ---------------------------------------------------
template<int MODE> __device__ __forceinline__ const float* mmA() {
    if (MODE == 0) return d_pooled;
    if (MODE == 1) return d_query;
    if (MODE == 2) return d_AW;
    return d_C1;
}
template<int MODE> struct MM {
    static const int TRANSB = (MODE == 2) ? 1 : 0;
    static const int LDA    = (MODE == 2) ? NBUF : D;
    static const int NTOT   = (MODE == 1) ? NBUF : D;
    static const int KSL    = (MODE == 0 || MODE == 3) ? 128 : 512;
};

// ---------------- split-precision bf16 mma GEMM, double-buffered ---------------
template<int MODE>
__global__ void __launch_bounds__(256) k_mm(const float* __restrict__ B, int ldb) {
    const int TRANSB = MM<MODE>::TRANSB;
    const int lda = MM<MODE>::LDA, Ntot = MM<MODE>::NTOT, Kslice = MM<MODE>::KSL;
    const float* __restrict__ A = mmA<MODE>();
    extern __shared__ __nv_bfloat16 sm_[];
    __nv_bfloat16* sAhi = sm_;                                   // [2][64*PAD]
    __nv_bfloat16* sAlo = sm_ + 2 * 64 * PAD;
    __nv_bfloat16* sBhi = sm_ + 4 * 64 * PAD;                    // [2][128*PAD]
    __nv_bfloat16* sBlo = sm_ + 4 * 64 * PAD + 2 * 128 * PAD;

    const int tid = threadIdx.x, lane = tid & 31, w = tid >> 5;
    const int wm = w >> 2, wn = w & 3;
    const int g = lane >> 2, t2 = (lane & 3) * 2;
    const int n0 = blockIdx.x * 128;
    const int kbase = blockIdx.y * Kslice;
    const int nct = Kslice >> 5;

    float acc[2][4][4];
#pragma unroll
    for (int f = 0; f < 2; f++)
#pragma unroll
        for (int q = 0; q < 4; q++)
#pragma unroll
            for (int i = 0; i < 4; i++) acc[f][q][i] = 0.f;

    float4 ra[2], rb[4];
    auto loadT = [&](int c) {
        const int k0 = kbase + c * 32;
#pragma unroll
        for (int j = 0; j < 2; j++) {
            int idx = tid * 2 + j, m = idx >> 3, c4 = (idx & 7) * 4;
            ra[j] = *(const float4*)&A[(size_t)m * lda + k0 + c4];
        }
        if (!TRANSB) {
#pragma unroll
            for (int j = 0; j < 4; j++) {
                int idx = tid * 4 + j, r = idx >> 3, c4 = (idx & 7) * 4;
                rb[j] = *(const float4*)&B[(size_t)(n0 + r) * ldb + k0 + c4];
            }
        } else {
            int cc = tid & 127, rbse = (tid >> 7) * 4;
#pragma unroll
            for (int j = 0; j < 4; j++) {
                int rr = rbse + j * 8;
                rb[j].x = B[(size_t)(k0 + rr + 0) * ldb + n0 + cc];
                rb[j].y = B[(size_t)(k0 + rr + 1) * ldb + n0 + cc];
                rb[j].z = B[(size_t)(k0 + rr + 2) * ldb + n0 + cc];
                rb[j].w = B[(size_t)(k0 + rr + 3) * ldb + n0 + cc];
            }
        }
    };
    auto storeT = [&](int buf) {
        int abase = buf * 64 * PAD, bbase = buf * 128 * PAD;
#pragma unroll
        for (int j = 0; j < 2; j++) {
            int idx = tid * 2 + j, m = idx >> 3, c4 = (idx & 7) * 4;
            uint2 H, L; split4(ra[j], H, L);
            *(uint2*)&sAhi[abase + m * PAD + c4] = H;
            *(uint2*)&sAlo[abase + m * PAD + c4] = L;
        }
        if (!TRANSB) {
#pragma unroll
            for (int j = 0; j < 4; j++) {
                int idx = tid * 4 + j, r = idx >> 3, c4 = (idx & 7) * 4;
                uint2 H, L; split4(rb[j], H, L);
                *(uint2*)&sBhi[bbase + r * PAD + c4] = H;
                *(uint2*)&sBlo[bbase + r * PAD + c4] = L;
            }
        } else {
            int cc = tid & 127, rbse = (tid >> 7) * 4;
#pragma unroll
            for (int j = 0; j < 4; j++) {
                int rr = rbse + j * 8;
                uint2 H, L; split4(rb[j], H, L);
                *(uint2*)&sBhi[bbase + cc * PAD + rr] = H;
                *(uint2*)&sBlo[bbase + cc * PAD + rr] = L;
            }
        }
    };

    loadT(0);
    storeT(0);
    __syncthreads();
    int buf = 0;
    for (int c = 0; c < nct; c++) {
        bool more = (c + 1 < nct);
        if (more) loadT(c + 1);
        const int abase = buf * 64 * PAD, bbase = buf * 128 * PAD;
#pragma unroll
        for (int ks = 0; ks < 32; ks += 16) {
            const int cA = ks + t2;
            uint32_t ahi[2][4], alo[2][4];
#pragma unroll
            for (int f = 0; f < 2; f++) {
                int rabs = abase + (wm * 32 + f * 16 + g) * PAD;
                ahi[f][0] = *(const uint32_t*)&sAhi[rabs + cA];
                ahi[f][1] = *(const uint32_t*)&sAhi[rabs + 8 * PAD + cA];
                ahi[f][2] = *(const uint32_t*)&sAhi[rabs + cA + 8];
                ahi[f][3] = *(const uint32_t*)&sAhi[rabs + 8 * PAD + cA + 8];
                alo[f][0] = *(const uint32_t*)&sAlo[rabs + cA];
                alo[f][1] = *(const uint32_t*)&sAlo[rabs + 8 * PAD + cA];
                alo[f][2] = *(const uint32_t*)&sAlo[rabs + cA + 8];
                alo[f][3] = *(const uint32_t*)&sAlo[rabs + 8 * PAD + cA + 8];
            }
#pragma unroll
            for (int nb = 0; nb < 4; nb++) {
                int ncb = bbase + (wn * 32 + nb * 8 + g) * PAD;
                uint32_t bh0 = *(const uint32_t*)&sBhi[ncb + cA];
                uint32_t bh1 = *(const uint32_t*)&sBhi[ncb + cA + 8];
                uint32_t bl0 = *(const uint32_t*)&sBlo[ncb + cA];
                uint32_t bl1 = *(const uint32_t*)&sBlo[ncb + cA + 8];
#pragma unroll
                for (int f = 0; f < 2; f++) {
                    mma16816(acc[f][nb], ahi[f], bh0, bh1);
                    mma16816(acc[f][nb], ahi[f], bl0, bl1);
                    mma16816(acc[f][nb], alo[f], bh0, bh1);
                }
            }
        }
        if (more) storeT(buf ^ 1);
        __syncthreads();
        buf ^= 1;
    }

    float* Cp = d_part + (size_t)blockIdx.y * 64 * Ntot;
    int r0 = wm * 32 + g;
#pragma unroll
    for (int f = 0; f < 2; f++)
#pragma unroll
        for (int nb = 0; nb < 4; nb++) {
            int rr = r0 + f * 16;
            int col = n0 + wn * 32 + nb * 8 + t2;
            *(float2*)&Cp[(size_t)rr * Ntot + col] =
                make_float2(acc[f][nb][0], acc[f][nb][1]);
            *(float2*)&Cp[(size_t)(rr + 8) * Ntot + col] =
                make_float2(acc[f][nb][2], acc[f][nb][3]);
        }
}

// ---------------- fp32 sample check ------------------------------------------
template<int CHK>
__global__ void k_check(const float* __restrict__ B, int ldb,
                        const float* __restrict__ bias) {
    const float* __restrict__ A   = (CHK == 0) ? d_pooled : d_AW;
    const float* __restrict__ Cc  = (CHK == 0) ? d_query : d_C1;
    const int lda = (CHK == 0) ? D : NBUF;
    const int K   = (CHK == 0) ? D : NBUF;
    int gw = (blockIdx.x * blockDim.x + threadIdx.x) >> 5;
    int lane = threadIdx.x & 31;
    int row = (gw * 37) & 63;
    int col = (int)((gw * 2654435761u) % (unsigned)D);
    float s = 0.f;
    if (CHK == 0) {
        for (int k = lane; k < K; k += 32)
            s += A[(size_t)row * lda + k] * B[(size_t)col * ldb + k];
    } else {
        for (int k = lane; k < K; k += 32)
            s += A[(size_t)row * lda + k] * B[(size_t)k * ldb + col];
    }
#pragma unroll
    for (int o = 16; o; o >>= 1) s += __shfl_xor_sync(0xFFFFFFFFu, s, o);
    if (lane == 0) {
        float ref = s + (bias ? bias[col] : 0.f);
        float got = Cc[(size_t)row * D + col];
        float tol = 0.02f * fabsf(ref) + 1e-3f;
        if (!(fabsf(got - ref) <= tol)) {
            if (CHK == 0) atomicExch(&d_flag0, 1);
            else          atomicExch(&d_flag1, 1);
        }
    }
}

// ---------------- f32x2 fallback GEMM (flag-gated) ----------------------------
template<int FM>
__global__ void __launch_bounds__(256) k_fp(const float* __restrict__ B, int ldb,
                                            const float* __restrict__ bias,
                                            float* __restrict__ outp) {
    if (((FM == 2) ? d_flag1 : d_flag0) == 0) return;
    const float* __restrict__ A = (FM == 0) ? d_pooled : (FM == 1) ? d_query
                                 : (FM == 2) ? d_AW : d_C1;
    float* __restrict__ Cout = (FM == 0) ? d_query : (FM == 1) ? d_base
                               : (FM == 2) ? d_C1 : outp;
    const int lda  = (FM == 2) ? NBUF : D;
    const int K    = (FM == 2) ? NBUF : D;
    const int Ntot = (FM == 1) ? NBUF : D;
    const int TRANSB = (FM == 2) ? 1 : 0;
    const float scale = (FM == 1) ? 0.022097086912079608f : 1.0f;

    __shared__ float As[32][64];
    __shared__ float Bs[32][128];
    const int tid = threadIdx.x, tx = tid & 15, ty = tid >> 4;
    const int n0 = blockIdx.x * 128;
    double acc[4][4];
#pragma unroll
    for (int i = 0; i < 4; i++)
#pragma unroll
        for (int j = 0; j < 4; j++) acc[i][j] = 0.0;

    for (int k0 = 0; k0 < K; k0 += 32) {
#pragma unroll
        for (int j = 0; j < 2; j++) {
            int idx = tid * 2 + j, m = idx >> 3, c4 = idx & 7;
            float4 v = *(const float4*)&A[(size_t)m * lda + k0 + c4 * 4];
            As[c4 * 4 + 0][m] = v.x; As[c4 * 4 + 1][m] = v.y;
            As[c4 * 4 + 2][m] = v.z; As[c4 * 4 + 3][m] = v.w;
        }
        if (!TRANSB) {
#pragma unroll
            for (int j = 0; j < 4; j++) {
                int idx = tid * 4 + j, n = idx >> 3, c4 = idx & 7;
                float4 v = *(const float4*)&B[(size_t)(n0 + n) * ldb + k0 + c4 * 4];
                Bs[c4 * 4 + 0][n] = v.x; Bs[c4 * 4 + 1][n] = v.y;
                Bs[c4 * 4 + 2][n] = v.z; Bs[c4 * 4 + 3][n] = v.w;
            }
        } else {
#pragma unroll
            for (int j = 0; j < 4; j++) {
                int idx = tid * 4 + j, kk = idx >> 5, n4 = idx & 31;
                *(float4*)&Bs[kk][n4 * 4] =
                    *(const float4*)&B[(size_t)(k0 + kk) * ldb + n0 + n4 * 4];
            }
        }
        __syncthreads();
#pragma unroll 8
        for (int kk = 0; kk < 32; kk++) {
            float4 av = *(const float4*)&As[kk][ty * 4];
            double2 b01 = *(const double2*)&Bs[kk][tx * 8];
            double2 b23 = *(const double2*)&Bs[kk][tx * 8 + 4];
            double a0 = pack_dup(av.x), a1 = pack_dup(av.y);
            double a2 = pack_dup(av.z), a3 = pack_dup(av.w);
            fma2(acc[0][0], a0, b01.x); fma2(acc[0][1], a0, b01.y);
            fma2(acc[0][2], a0, b23.x); fma2(acc[0][3], a0, b23.y);
            fma2(acc[1][0], a1, b01.x); fma2(acc[1][1], a1, b01.y);
            fma2(acc[1][2], a1, b23.x); fma2(acc[1][3], a1, b23.y);
            fma2(acc[2][0], a2, b01.x); fma2(acc[2][1], a2, b01.y);
            fma2(acc[2][2], a2, b23.x); fma2(acc[2][3], a2, b23.y);
            fma2(acc[3][0], a3, b01.x); fma2(acc[3][1], a3, b01.y);
            fma2(acc[3][2], a3, b23.x); fma2(acc[3][3], a3, b23.y);
        }
        __syncthreads();
    }
    float ws = d_wsum;
#pragma unroll
    for (int i = 0; i < 4; i++) {
        int row = ty * 4 + i;
        float o[8];
        unpack2(acc[i][0], o[0], o[1]); unpack2(acc[i][1], o[2], o[3]);
        unpack2(acc[i][2], o[4], o[5]); unpack2(acc[i][3], o[6], o[7]);
#pragma unroll
        for (int j = 0; j < 8; j++) {
            int col = n0 + tx * 8 + j;
            float c = o[j] * scale;
            if (FM == 3)       c = (ws > 0.f) ? c / fmaxf(ws, 1e-8f) + bias[col] : 0.f;
            else if (FM == 0)  c += bias[col];
            Cout[(size_t)row * Ntot + col] = c;
        }
    }
}

// ---------------- valid_mask dtype detection ----------------------------------
__global__ void k_detect(const void* vm) {
    __shared__ int mode;
    if (threadIdx.x == 0) {
        const float* fp = (const float*)vm;
        const int*   ip = (const int*)vm;
        bool isF = true, isI = true;
        for (int k = 0; k < 64; k++) {
            float f = fp[k];
            if (!(f == 0.0f || f == 1.0f)) isF = false;
            int v = ip[k];
            if (!(v == 0 || v == 1)) isI = false;
        }
        mode = isF ? 2 : (isI ? 1 : 0);
    }
    __syncthreads();
    int m = mode;
    const unsigned char* cp = (const unsigned char*)vm;
    const int*   ip = (const int*)vm;
    const float* fp = (const float*)vm;
    for (int n = threadIdx.x; n < NBUF; n += blockDim.x) {
        float v;
        if (m == 2)      v = (fp[n] != 0.0f) ? 1.f : 0.f;
        else if (m == 1) v = (ip[n] != 0)    ? 1.f : 0.f;
        else             v = (cp[n] != 0)    ? 1.f : 0.f;
        d_validf[n] = v;
    }
}

__global__ void k_init() {
    int i = threadIdx.x;
    if (i <= ROUNDS) d_active[i] = 0.f;
    if (i == 0) { d_wsum = 0.f; d_flag0 = 0; d_flag1 = 0; }
}

// ---------------- masked mean pool -------------------------------------------
__global__ void __launch_bounds__(256) k_pool(const float* __restrict__ qs,
                                              const float* __restrict__ mask) {
    int b = blockIdx.y;
    int d = blockIdx.x * 256 + threadIdx.x;
    __shared__ float sm[T];
    __shared__ float red[256];
    for (int t = threadIdx.x; t < T; t += 256) sm[t] = mask[b * T + t];
    __syncthreads();
    red[threadIdx.x] = sm[threadIdx.x] + sm[threadIdx.x + 256];
    __syncthreads();
    for (int off = 128; off > 0; off >>= 1) {
        if (threadIdx.x < off) red[threadIdx.x] += red[threadIdx.x + off];
        __syncthreads();
    }
    float msum = red[0];
    const float* base = qs + ((size_t)b * T) * D + d;
    float a0 = 0, a1 = 0, a2 = 0, a3 = 0;
#pragma unroll 2
    for (int t = 0; t < T; t += 8) {
        a0 += base[(size_t)(t + 0) * D] * sm[t + 0];
        a1 += base[(size_t)(t + 1) * D] * sm[t + 1];
        a2 += base[(size_t)(t + 2) * D] * sm[t + 2];
        a3 += base[(size_t)(t + 3) * D] * sm[t + 3];
        a0 += base[(size_t)(t + 4) * D] * sm[t + 4];
        a1 += base[(size_t)(t + 5) * D] * sm[t + 5];
        a2 += base[(size_t)(t + 6) * D] * sm[t + 6];
        a3 += base[(size_t)(t + 7) * D] * sm[t + 7];
    }
    d_pooled[b * D + d] = (a0 + a1 + a2 + a3) / (msum + 1e-8f);
}

// ---------------- split-K reduces ---------------------------------------------
__global__ void k_reduce_q(const float* __restrict__ bq) {
    int idx = blockIdx.x * 256 + threadIdx.x;
    if (idx >= Bb * D) return;
    float s = 0.f;
#pragma unroll
    for (int kz = 0; kz < 16; kz++) s += d_part[(size_t)kz * Bb * D + idx];
    d_query[idx] = s + bq[idx & (D - 1)];
}

__global__ void k_reduce_base() {
    int idx = blockIdx.x * 256 + threadIdx.x;
    float s = 0.f;
#pragma unroll
    for (int kz = 0; kz < 4; kz++) s += d_part[(size_t)kz * Bb * NBUF + idx];
    d_base[idx] = s * 0.022097086912079608f;
}

__global__ void k_reduce_c1() {
    int idx = blockIdx.x * 256 + threadIdx.x;
    if (idx >= Bb * D) return;
    float s = 0.f;
#pragma unroll
    for (int kz = 0; kz < 32; kz++) s += d_part[(size_t)kz * Bb * D + idx];
    d_C1[idx] = s;
}

__global__ void k_reduce_out(const float* __restrict__ bc, float* __restrict__ out) {
    int idx = blockIdx.x * 256 + threadIdx.x;
    if (idx >= Bb * D) return;
    float ws = d_wsum;
    if (ws > 0.f) {
        float s = 0.f;
#pragma unroll
        for (int kz = 0; kz < 16; kz++) s += d_part[(size_t)kz * Bb * D + idx];
        out[idx] = s / fmaxf(ws, 1e-8f) + bc[idx & (D - 1)];
    } else {
        out[idx] = 0.f;
    }
}

// ---------------- persistent round-loop kernel --------------------------------
__device__ __forceinline__ void gridbar() {
    __syncthreads();
    if (threadIdx.x == 0) {
        __threadfence();
        unsigned g = atomicAdd(&d_bar_gen, 0u);
        if (atomicAdd(&d_bar_cnt, 1u) == GRIDB - 1u) {
            d_bar_cnt = 0u;
            __threadfence();
            atomicAdd(&d_bar_gen, 1u);
        } else {
            while (atomicAdd(&d_bar_gen, 0u) == g) { }
        }
        __threadfence();
    }
    __syncthreads();
}

__global__ void __launch_bounds__(256) k_rounds(const float* __restrict__ prio,
                                                const float* __restrict__ ages) {
    const int tid = threadIdx.x, blk = blockIdx.x;
    __shared__ float red[256];
    __shared__ float invs[64];
    const float DK = -0.105360515657826301f;  // ln(0.9)
    const int col = blk * 128 + (tid & 127);
    const int blo = (tid >> 7) * 32;

    float w  = ages[col];
    float p  = prio[col];
    float vf = d_validf[col];
    float aw_acc[32];
#pragma unroll
    for (int j = 0; j < 32; j++) aw_acc[j] = 0.f;

    // prologue: g(0) + active(0)
    {
        float a = 0.f;
        if (tid < 128) {
            float eff = p * __expf(w * DK);
            float act = vf / (1.f + __expf((0.5f - eff) * 10.f));
            __stcg(&d_g[col], act * eff);
            a = act;
        }
        red[tid] = a; __syncthreads();
        for (int off = 128; off; off >>= 1) {
            if (tid < off) red[tid] += red[tid + off];
            __syncthreads();
        }
        if (tid == 0) atomicAdd(&d_active[0], red[0]);
    }
    gridbar();

    float wsum = 0.f, rw = 1.f;
    for (int r = 0; r < ROUNDS; r++) {
        if (__ldcg(&d_active[r]) < 0.5f) break;
        wsum += rw;

        // ---- Phase B: e -> E (d_part), rowsum partials
        {
            int b   = blk >> 1;
            int n0b = (blk & 1) * (NBUF / 2);
            const float* br = d_base + (size_t)b * NBUF + n0b;
            float* er = d_part + (size_t)b * NBUF + n0b;
            float ps = 0.f;
            for (int i = tid; i < NBUF / 2; i += 256) {
                int n = n0b + i;
                float e = d_validf[n] * __expf(br[i] * __ldcg(&d_g[n]));
                __stcg(&er[i], e);
                ps += e;
            }
            red[tid] = ps; __syncthreads();
            for (int off = 128; off; off >>= 1) {
                if (tid < off) red[tid] += red[tid + off];
                __syncthreads();
            }
            if (tid == 0) __stcg(&d_rs_part[(blk & 1) * Bb + b], red[0]);
        }
        gridbar();

        // ---- Phase C: aw from E; AW in regs; wages update; g(r+1), active(r+1)
        {
            if (tid < 64)
                invs[tid] = 1.f / (__ldcg(&d_rs_part[tid]) + __ldcg(&d_rs_part[Bb + tid]));
            __syncthreads();
            float cs = 0.f;
#pragma unroll 8
            for (int j = 0; j < 32; j++) {
                int bb = blo + j;
                float e = __ldcg(&d_part[(size_t)bb * NBUF + col]) * invs[bb];
                aw_acc[j] += rw * e;
                cs += e;
            }
            __syncthreads();
            red[tid] = cs; __syncthreads();
            float act = 0.f;
            if (tid < 128) {
                w += (red[tid] + red[tid + 128]) * (1.f / 64.f);
                float eff = p * __expf(w * DK);
                act = vf / (1.f + __expf((0.5f - eff) * 10.f));
                __stcg(&d_g[col], act * eff);
            }
            __syncthreads();
            red[tid] = act; __syncthreads();
            for (int off = 128; off; off >>= 1) {
                if (tid < off) red[tid] += red[tid + off];
                __syncthreads();
            }
            if (tid == 0) atomicAdd(&d_active[r + 1], red[0]);
        }
        gridbar();
        rw *= 0.9f;
    }
    // final AW store (covers early-break: zeros)
#pragma unroll 8
    for (int j = 0; j < 32; j++)
        d_AW[(size_t)(blo + j) * NBUF + col] = aw_acc[j];
    if (blk == 0 && tid == 0) d_wsum = wsum;
}

// ---------------- launch ------------------------------------------------------
extern "C" void kernel_launch(void* const* d_in, const int* in_sizes, int n_in,
                              void* d_out, int out_size) {
    const float* qs     = (const float*)d_in[0];
    const float* amask  = (const float*)d_in[1];
    const float* keys   = (const float*)d_in[2];
    const float* values = (const float*)d_in[3];
    const float* prio   = (const float*)d_in[4];
    const float* ages   = (const float*)d_in[5];
    const void*  vmask  = d_in[6];
    const float* Wq     = (const float*)d_in[7];
    const float* bq     = (const float*)d_in[8];
    const float* Wc     = (const float*)d_in[9];
    const float* bc     = (const float*)d_in[10];
    float* out = (float*)d_out;

    cudaFuncSetAttribute(k_mm<0>, cudaFuncAttributeMaxDynamicSharedMemorySize, SMEM_MM);
    cudaFuncSetAttribute(k_mm<1>, cudaFuncAttributeMaxDynamicSharedMemorySize, SMEM_MM);
    cudaFuncSetAttribute(k_mm<2>, cudaFuncAttributeMaxDynamicSharedMemorySize, SMEM_MM);
    cudaFuncSetAttribute(k_mm<3>, cudaFuncAttributeMaxDynamicSharedMemorySize, SMEM_MM);

    k_detect<<<1, 256>>>(vmask);
    k_init<<<1, 256>>>();
    k_pool<<<dim3(8, 64), 256>>>(qs, amask);

    // query = pooled @ Wq^T + bq  (mma split-K=16; checked; f32x2 fallback)
    k_mm<0><<<dim3(16, 16), 256, SMEM_MM>>>(Wq, D);
    k_reduce_q<<<(Bb * D + 255) / 256, 256>>>(bq);
    k_check<0><<<8, 256>>>(Wq, D, bq);
    k_fp<0><<<16, 256>>>(Wq, D, bq, (float*)0);

    // base = query @ keys^T * SC  (mma split-K=4; gated by flag0)
    k_mm<1><<<dim3(128, 4), 256, SMEM_MM>>>(keys, D);
    k_reduce_base<<<(Bb * NBUF) / 256, 256>>>();
    k_fp<1><<<128, 256>>>(keys, D, (const float*)0, (float*)0);

    k_rounds<<<GRIDB, 256>>>(prio, ages);

    // C1 = AW @ values  (mma split-K=32; checked; fallback)
    k_mm<2><<<dim3(16, 32), 256, SMEM_MM>>>(values, D);
    k_reduce_c1<<<(Bb * D + 255) / 256, 256>>>();
    k_check<1><<<2, 256>>>(values, D, (const float*)0);
    k_fp<2><<<16, 256>>>(values, D, (const float*)0, (float*)0);

    // out = (C1 @ Wc^T)/wsum + bc
    k_mm<3><<<dim3(16, 16), 256, SMEM_MM>>>(Wc, D);
    k_reduce_out<<<(Bb * D + 255) / 256, 256>>>(bc, out);
    k_fp<3><<<16, 256>>>(Wc, D, bc, out);
}